// round 14
// baseline (speedup 1.0000x reference)
#include <cuda_runtime.h>
#include <cuda_fp16.h>
#include <math.h>
#include <stdint.h>

// Problem constants
#define Bn 4
#define Tn 2048
#define Cn 1024
#define Hn 16
#define Dn 64
#define Mn (Bn*Tn)   // 8192 token rows

// fp16 operands (g_w16 contiguous: rows [0,3072) = Wq|Wk|Wv, [3072,4096) = Wo)
__device__ __half g_x16[(size_t)Mn*Cn];
__device__ __half g_w16[4][(size_t)Cn*Cn];
__device__ __half g_a16[(size_t)Mn*Cn];    // attention output
__device__ __half g_q16[(size_t)Mn*Cn];    // Q (post-GEMM; rope in place, scaled 1/8)
__device__ __half g_k16[(size_t)Mn*Cn];    // K
__device__ __half g_v16[(size_t)Mn*Cn];    // V

// ---------------------------------------------------------------------------
// common PTX helpers
// ---------------------------------------------------------------------------
static __device__ __forceinline__ void cp_async16(uint32_t dst, const void* src) {
    asm volatile("cp.async.cg.shared.global [%0], [%1], 16;\n" :: "r"(dst), "l"(src));
}
static __device__ __forceinline__ void cp_commit() {
    asm volatile("cp.async.commit_group;\n");
}
static __device__ __forceinline__ void cp_wait1() {
    asm volatile("cp.async.wait_group 1;\n");
}
static __device__ __forceinline__ void ldmatrix_x4(uint32_t &r0, uint32_t &r1,
                                                   uint32_t &r2, uint32_t &r3, uint32_t addr) {
    asm volatile("ldmatrix.sync.aligned.m8n8.x4.shared.b16 {%0,%1,%2,%3}, [%4];\n"
                 : "=r"(r0), "=r"(r1), "=r"(r2), "=r"(r3) : "r"(addr));
}
static __device__ __forceinline__ void ldmatrix_x4_trans(uint32_t &r0, uint32_t &r1,
                                                         uint32_t &r2, uint32_t &r3, uint32_t addr) {
    asm volatile("ldmatrix.sync.aligned.m8n8.x4.trans.shared.b16 {%0,%1,%2,%3}, [%4];\n"
                 : "=r"(r0), "=r"(r1), "=r"(r2), "=r"(r3) : "r"(addr));
}
static __device__ __forceinline__ void mma_fp16(float* d, const uint32_t* a,
                                                uint32_t b0, uint32_t b1) {
    asm volatile(
        "mma.sync.aligned.m16n8k16.row.col.f32.f16.f16.f32 "
        "{%0,%1,%2,%3}, {%4,%5,%6,%7}, {%8,%9}, {%0,%1,%2,%3};\n"
        : "+f"(d[0]), "+f"(d[1]), "+f"(d[2]), "+f"(d[3])
        : "r"(a[0]), "r"(a[1]), "r"(a[2]), "r"(a[3]), "r"(b0), "r"(b1));
}
static __device__ __forceinline__ uint32_t pack_fp16(float lo, float hi) {
    uint32_t d;
    asm volatile("cvt.rn.f16x2.f32 %0, %1, %2;\n" : "=r"(d) : "f"(hi), "f"(lo));
    return d;
}

// ---------------------------------------------------------------------------
// fp32 -> fp16 converts
// ---------------------------------------------------------------------------
__global__ __launch_bounds__(256) void conv_fp16(
    const float* __restrict__ src, __half* __restrict__ dst, int n4)
{
    int i = blockIdx.x * 256 + threadIdx.x;
    if (i >= n4) return;
    float4 v = ((const float4*)src)[i];
    uint2 o;
    o.x = pack_fp16(v.x, v.y);
    o.y = pack_fp16(v.z, v.w);
    ((uint2*)dst)[i] = o;
}

__global__ __launch_bounds__(256) void conv_w4(
    const float* __restrict__ w0, const float* __restrict__ w1,
    const float* __restrict__ w2, const float* __restrict__ w3,
    __half* __restrict__ dst)
{
    const float* srcs[4] = { w0, w1, w2, w3 };
    const int m = blockIdx.y;
    const int i = blockIdx.x * 256 + threadIdx.x;   // < Cn*Cn/4
    float4 v = ((const float4*)srcs[m])[i];
    uint2 o;
    o.x = pack_fp16(v.x, v.y);
    o.y = pack_fp16(v.z, v.w);
    ((uint2*)(dst + (size_t)m * Cn * Cn))[i] = o;
}

// ---------------------------------------------------------------------------
// Shared GEMM mainloop pieces (128x128x32 tile, 8 warps, m16n8k16.f16)
// ---------------------------------------------------------------------------
#define BM 128
#define BN 128
#define BKH 32
#define STAGES 3
#define ATILE_BYTES (BM*BKH*2)          // 8192
#define STAGE_BYTES (2*ATILE_BYTES)     // 16384

// The mainloop body is duplicated in two kernels that differ only in epilogue.

// ---- QKV fused GEMM: A[M,K] * Wqkv[3072,K]^T, fp16 outputs split by matrix ----
__global__ __launch_bounds__(256) void gemm_qkv(
    const __half* __restrict__ A, const __half* __restrict__ W,
    __half* __restrict__ Q, __half* __restrict__ Ko, __half* __restrict__ V)
{
    __shared__ __align__(16) char smem[STAGES * STAGE_BYTES];
    const int K = Cn;

    const int tid  = threadIdx.x;
    const int lane = tid & 31;
    const int wid  = tid >> 5;
    const int wm   = wid >> 2;
    const int wn   = wid & 3;
    const int rowBase = blockIdx.y * BM;
    const int colBase = blockIdx.x * BN;    // 0..2944

    const uint32_t sbase = (uint32_t)__cvta_generic_to_shared(smem);

    const int lr = tid >> 2;
    const int lc = tid & 3;
    const uint32_t swz = (uint32_t)(lc ^ ((lr >> 1) & 3));
    const uint32_t dA0 = sbase + (uint32_t)lr * 64 + (swz << 4);
    const __half* pA0 = A + (size_t)(rowBase + lr) * K + lc * 8;
    const __half* pA1 = A + (size_t)(rowBase + lr + 64) * K + lc * 8;
    const __half* pW0 = W + (size_t)(colBase + lr) * K + lc * 8;
    const __half* pW1 = W + (size_t)(colBase + lr + 64) * K + lc * 8;

    uint32_t aoff[4]; uint32_t asw[4];
#pragma unroll
    for (int mt = 0; mt < 4; mt++) {
        int r = wm * 64 + mt * 16 + (lane & 15);
        aoff[mt] = (uint32_t)r * 64;
        asw[mt]  = (uint32_t)((r >> 1) & 3);
    }
    const uint32_t alo = (uint32_t)((lane >> 4) & 1);
    uint32_t boff[2]; uint32_t bsw[2];
#pragma unroll
    for (int p = 0; p < 2; p++) {
        int r = wn * 32 + p * 16 + ((lane >> 4) << 3) + (lane & 7);
        boff[p] = (uint32_t)(ATILE_BYTES) + (uint32_t)r * 64;
        bsw[p]  = (uint32_t)((r >> 1) & 3);
    }
    const uint32_t blo = (uint32_t)((lane >> 3) & 1);

    float acc[4][4][4];
#pragma unroll
    for (int i = 0; i < 4; i++)
#pragma unroll
        for (int j = 0; j < 4; j++)
#pragma unroll
            for (int v = 0; v < 4; v++) acc[i][j][v] = 0.0f;

    const int nIters = K / BKH;

#pragma unroll
    for (int s = 0; s < 2; s++) {
        uint32_t sb = dA0 + s * STAGE_BYTES;
        int k0 = s * BKH;
        cp_async16(sb,                    pA0 + k0);
        cp_async16(sb + 4096,             pA1 + k0);
        cp_async16(sb + ATILE_BYTES,      pW0 + k0);
        cp_async16(sb + ATILE_BYTES+4096, pW1 + k0);
        cp_commit();
    }

    for (int it = 0; it < nIters; ++it) {
        cp_wait1();
        __syncthreads();

        if (it + 2 < nIters) {
            uint32_t sb = dA0 + ((it + 2) % STAGES) * STAGE_BYTES;
            int k0 = (it + 2) * BKH;
            cp_async16(sb,                    pA0 + k0);
            cp_async16(sb + 4096,             pA1 + k0);
            cp_async16(sb + ATILE_BYTES,      pW0 + k0);
            cp_async16(sb + ATILE_BYTES+4096, pW1 + k0);
        }
        cp_commit();

        const uint32_t sb = sbase + (uint32_t)((it % STAGES) * STAGE_BYTES);
#pragma unroll
        for (int ks = 0; ks < 2; ks++) {
            uint32_t a[4][4], b[4][2];
#pragma unroll
            for (int mt = 0; mt < 4; mt++) {
                uint32_t c = (uint32_t)(2 * ks) + alo;
                uint32_t addr = sb + aoff[mt] + ((c ^ asw[mt]) << 4);
                ldmatrix_x4(a[mt][0], a[mt][1], a[mt][2], a[mt][3], addr);
            }
#pragma unroll
            for (int p = 0; p < 2; p++) {
                uint32_t c = (uint32_t)(2 * ks) + blo;
                uint32_t addr = sb + boff[p] + ((c ^ bsw[p]) << 4);
                uint32_t r0, r1, r2, r3;
                ldmatrix_x4(r0, r1, r2, r3, addr);
                b[2*p][0] = r0; b[2*p][1] = r1;
                b[2*p+1][0] = r2; b[2*p+1][1] = r3;
            }
#pragma unroll
            for (int mt = 0; mt < 4; mt++)
#pragma unroll
                for (int nt = 0; nt < 4; nt++)
                    mma_fp16(acc[mt][nt], a[mt], b[nt][0], b[nt][1]);
        }
    }

    // epilogue: fp16 to the matrix selected by colBase
    const int matsel = colBase >> 10;           // 0=Q 1=K 2=V
    const int ccb    = colBase & 1023;
    __half* dst = (matsel == 0) ? Q : (matsel == 1) ? Ko : V;
#pragma unroll
    for (int mt = 0; mt < 4; mt++) {
        int r0 = rowBase + wm * 64 + mt * 16 + (lane >> 2);
#pragma unroll
        for (int nt = 0; nt < 4; nt++) {
            int cc = ccb + wn * 32 + nt * 8 + (lane & 3) * 2;
            *(uint32_t*)(dst + (size_t)r0 * Cn + cc) =
                pack_fp16(acc[mt][nt][0], acc[mt][nt][1]);
            *(uint32_t*)(dst + (size_t)(r0 + 8) * Cn + cc) =
                pack_fp16(acc[mt][nt][2], acc[mt][nt][3]);
        }
    }
}

// ---- Output projection GEMM: fp32 out ----
__global__ __launch_bounds__(256) void gemm_fp16(
    const __half* __restrict__ A, const __half* __restrict__ W,
    float* __restrict__ C, int M, int N, int K)
{
    __shared__ __align__(16) char smem[STAGES * STAGE_BYTES];

    const int tid  = threadIdx.x;
    const int lane = tid & 31;
    const int wid  = tid >> 5;
    const int wm   = wid >> 2;
    const int wn   = wid & 3;
    const int rowBase = blockIdx.y * BM;
    const int colBase = blockIdx.x * BN;

    const uint32_t sbase = (uint32_t)__cvta_generic_to_shared(smem);

    const int lr = tid >> 2;
    const int lc = tid & 3;
    const uint32_t swz = (uint32_t)(lc ^ ((lr >> 1) & 3));
    const uint32_t dA0 = sbase + (uint32_t)lr * 64 + (swz << 4);
    const __half* pA0 = A + (size_t)(rowBase + lr) * K + lc * 8;
    const __half* pA1 = A + (size_t)(rowBase + lr + 64) * K + lc * 8;
    const __half* pW0 = W + (size_t)(colBase + lr) * K + lc * 8;
    const __half* pW1 = W + (size_t)(colBase + lr + 64) * K + lc * 8;

    uint32_t aoff[4]; uint32_t asw[4];
#pragma unroll
    for (int mt = 0; mt < 4; mt++) {
        int r = wm * 64 + mt * 16 + (lane & 15);
        aoff[mt] = (uint32_t)r * 64;
        asw[mt]  = (uint32_t)((r >> 1) & 3);
    }
    const uint32_t alo = (uint32_t)((lane >> 4) & 1);
    uint32_t boff[2]; uint32_t bsw[2];
#pragma unroll
    for (int p = 0; p < 2; p++) {
        int r = wn * 32 + p * 16 + ((lane >> 4) << 3) + (lane & 7);
        boff[p] = (uint32_t)(ATILE_BYTES) + (uint32_t)r * 64;
        bsw[p]  = (uint32_t)((r >> 1) & 3);
    }
    const uint32_t blo = (uint32_t)((lane >> 3) & 1);

    float acc[4][4][4];
#pragma unroll
    for (int i = 0; i < 4; i++)
#pragma unroll
        for (int j = 0; j < 4; j++)
#pragma unroll
            for (int v = 0; v < 4; v++) acc[i][j][v] = 0.0f;

    const int nIters = K / BKH;

#pragma unroll
    for (int s = 0; s < 2; s++) {
        uint32_t sb = dA0 + s * STAGE_BYTES;
        int k0 = s * BKH;
        cp_async16(sb,                    pA0 + k0);
        cp_async16(sb + 4096,             pA1 + k0);
        cp_async16(sb + ATILE_BYTES,      pW0 + k0);
        cp_async16(sb + ATILE_BYTES+4096, pW1 + k0);
        cp_commit();
    }

    for (int it = 0; it < nIters; ++it) {
        cp_wait1();
        __syncthreads();

        if (it + 2 < nIters) {
            uint32_t sb = dA0 + ((it + 2) % STAGES) * STAGE_BYTES;
            int k0 = (it + 2) * BKH;
            cp_async16(sb,                    pA0 + k0);
            cp_async16(sb + 4096,             pA1 + k0);
            cp_async16(sb + ATILE_BYTES,      pW0 + k0);
            cp_async16(sb + ATILE_BYTES+4096, pW1 + k0);
        }
        cp_commit();

        const uint32_t sb = sbase + (uint32_t)((it % STAGES) * STAGE_BYTES);
#pragma unroll
        for (int ks = 0; ks < 2; ks++) {
            uint32_t a[4][4], b[4][2];
#pragma unroll
            for (int mt = 0; mt < 4; mt++) {
                uint32_t c = (uint32_t)(2 * ks) + alo;
                uint32_t addr = sb + aoff[mt] + ((c ^ asw[mt]) << 4);
                ldmatrix_x4(a[mt][0], a[mt][1], a[mt][2], a[mt][3], addr);
            }
#pragma unroll
            for (int p = 0; p < 2; p++) {
                uint32_t c = (uint32_t)(2 * ks) + blo;
                uint32_t addr = sb + boff[p] + ((c ^ bsw[p]) << 4);
                uint32_t r0, r1, r2, r3;
                ldmatrix_x4(r0, r1, r2, r3, addr);
                b[2*p][0] = r0; b[2*p][1] = r1;
                b[2*p+1][0] = r2; b[2*p+1][1] = r3;
            }
#pragma unroll
            for (int mt = 0; mt < 4; mt++)
#pragma unroll
                for (int nt = 0; nt < 4; nt++)
                    mma_fp16(acc[mt][nt], a[mt], b[nt][0], b[nt][1]);
        }
    }

#pragma unroll
    for (int mt = 0; mt < 4; mt++) {
        int r0 = rowBase + wm * 64 + mt * 16 + (lane >> 2);
#pragma unroll
        for (int nt = 0; nt < 4; nt++) {
            int cc = colBase + wn * 32 + nt * 8 + (lane & 3) * 2;
            *(float2*)(C + (size_t)r0 * N + cc) =
                make_float2(acc[mt][nt][0], acc[mt][nt][1]);
            *(float2*)(C + (size_t)(r0 + 8) * N + cc) =
                make_float2(acc[mt][nt][2], acc[mt][nt][3]);
        }
    }
}

// ---------------------------------------------------------------------------
// Fused RoPE + RMS-norm, IN PLACE on fp16 Q and K (Q post-scaled by 1/8).
// One warp per (token_row, head); lane holds dims lane and lane+32.
// ---------------------------------------------------------------------------
__global__ __launch_bounds__(256) void rope_rms_fp16(
    __half* __restrict__ q16, __half* __restrict__ k16,
    const float* __restrict__ cp, const float* __restrict__ sp)
{
    const int gw   = (blockIdx.x * 256 + threadIdx.x) >> 5;
    const int lane = threadIdx.x & 31;
    const int row  = gw >> 4;
    const int head = gw & 15;
    const int t    = row & (Tn - 1);

    const float c1 = cp[t * Dn + lane];
    const float c2 = cp[t * Dn + 32 + lane];
    const float s1 = sp[t * Dn + lane];
    const float s2 = sp[t * Dn + 32 + lane];

    const size_t base = (size_t)row * Cn + head * Dn;
    __half* bufs[2] = { q16 + base, k16 + base };
    const float postscale[2] = { 0.125f, 1.0f };

#pragma unroll
    for (int p = 0; p < 2; p++) {
        __half* buf = bufs[p];
        float x1 = __half2float(buf[lane]);
        float x2 = __half2float(buf[lane + 32]);
        float r1 = x1 * c1 - x2 * s1;
        float r2 = x2 * c2 + x1 * s2;
        float ss = r1 * r1 + r2 * r2;
#pragma unroll
        for (int off = 16; off >= 1; off >>= 1)
            ss += __shfl_xor_sync(0xffffffffu, ss, off);
        float scale = rsqrtf(ss * (1.0f / 64.0f) + 1e-6f) * postscale[p];
        buf[lane]      = __float2half(r1 * scale);
        buf[lane + 32] = __float2half(r2 * scale);
    }
}

// ---------------------------------------------------------------------------
// Tensor-core flash attention, single fp16, fp32 accumulate. (unchanged)
// ---------------------------------------------------------------------------
#define F_Q 0
#define F_ST 8192
#define F_TILE 8192
#define F_STAGE 16384
#define FLASH_SMEM (8192 + 2*16384)   // 40960

static __device__ __forceinline__ void load_tile64(uint32_t sdst,
                                                   const __half* g, int tid)
{
    int r = tid >> 1;
    int cb = (tid & 1) * 4;
    const char* src = (const char*)g + (size_t)r * (Cn * 2);
#pragma unroll
    for (int i = 0; i < 4; i++) {
        int c = cb + i;
        cp_async16(sdst + (uint32_t)r * 128 + (uint32_t)((c ^ (r & 7)) << 4),
                   src + c * 16);
    }
}

__global__ __launch_bounds__(128) void flash_tc(
    const __half* __restrict__ q16, const __half* __restrict__ k16,
    const __half* __restrict__ v16, __half* __restrict__ O)
{
    extern __shared__ __align__(1024) char smem[];
    const uint32_t sb = (uint32_t)__cvta_generic_to_shared(smem);

    const int tid  = threadIdx.x;
    const int w    = tid >> 5;
    const int lane = tid & 31;
    const int q0   = blockIdx.x * 64;
    const int h    = blockIdx.y;
    const int b    = blockIdx.z;
    const size_t rowbase = (size_t)b * Tn;
    const size_t qgoff = (rowbase + q0) * Cn + h * Dn;
    const size_t kgoff = rowbase * Cn + h * Dn;

    load_tile64(sb + F_Q, q16 + qgoff, tid);
    load_tile64(sb + F_ST + 0*F_TILE, k16 + kgoff, tid);
    load_tile64(sb + F_ST + 1*F_TILE, v16 + kgoff, tid);
    cp_commit();

    const int qrow = 16 * w + ((lane >> 3) & 1) * 8 + (lane & 7);
    const uint32_t qrb = (uint32_t)qrow * 128;
    const uint32_t qrs = (uint32_t)(qrow & 7);
    const uint32_t ahi = (uint32_t)(lane >> 4);
    const int krow0 = (lane >> 4) * 8 + (lane & 7);
    const uint32_t kck = (uint32_t)((lane >> 3) & 1);
    const int vrow0 = ((lane >> 3) & 1) * 8 + (lane & 7);
    const uint32_t vck = (uint32_t)(lane >> 4);

    float o[8][4];
#pragma unroll
    for (int t = 0; t < 8; t++)
#pragma unroll
        for (int j = 0; j < 4; j++) o[t][j] = 0.0f;
    float m0 = -1e30f, m1 = -1e30f, l0 = 0.0f, l1 = 0.0f;

    const int NKT = Tn / 64;
    for (int kt = 0; kt < NKT; kt++) {
        if (kt + 1 < NKT) {
            const size_t goff = kgoff + (size_t)(kt + 1) * 64 * Cn;
            uint32_t st = sb + F_ST + ((kt + 1) & 1) * F_STAGE;
            load_tile64(st,          k16 + goff, tid);
            load_tile64(st + F_TILE, v16 + goff, tid);
        }
        cp_commit();
        cp_wait1();
        __syncthreads();

        const uint32_t st = sb + F_ST + (kt & 1) * F_STAGE;
        const uint32_t sK = st, sV = st + F_TILE;

        float s[8][4];
#pragma unroll
        for (int t = 0; t < 8; t++)
#pragma unroll
            for (int j = 0; j < 4; j++) s[t][j] = 0.0f;

#pragma unroll
        for (int ks = 0; ks < 4; ks++) {
            uint32_t aq[4];
            {
                uint32_t c = (uint32_t)(2 * ks) + ahi;
                uint32_t off = qrb + ((c ^ qrs) << 4);
                ldmatrix_x4(aq[0], aq[1], aq[2], aq[3], sb + F_Q + off);
            }
#pragma unroll
            for (int p = 0; p < 4; p++) {
                int r = 16 * p + krow0;
                uint32_t c = (uint32_t)(2 * ks) + kck;
                uint32_t off = (uint32_t)r * 128 + ((c ^ (uint32_t)(r & 7)) << 4);
                uint32_t b0, b1, b2, b3;
                ldmatrix_x4(b0, b1, b2, b3, sK + off);
                mma_fp16(s[2*p],   aq, b0, b1);
                mma_fp16(s[2*p+1], aq, b2, b3);
            }
        }

        float mx0 = -1e30f, mx1 = -1e30f;
#pragma unroll
        for (int t = 0; t < 8; t++) {
            mx0 = fmaxf(mx0, fmaxf(s[t][0], s[t][1]));
            mx1 = fmaxf(mx1, fmaxf(s[t][2], s[t][3]));
        }
        mx0 = fmaxf(mx0, __shfl_xor_sync(0xffffffffu, mx0, 1));
        mx0 = fmaxf(mx0, __shfl_xor_sync(0xffffffffu, mx0, 2));
        mx1 = fmaxf(mx1, __shfl_xor_sync(0xffffffffu, mx1, 1));
        mx1 = fmaxf(mx1, __shfl_xor_sync(0xffffffffu, mx1, 2));
        float mn0 = fmaxf(m0, mx0), mn1 = fmaxf(m1, mx1);
        float al0 = __expf(m0 - mn0), al1 = __expf(m1 - mn1);
        m0 = mn0; m1 = mn1;

        float rs0 = 0.0f, rs1 = 0.0f;
        uint32_t pph[8][2];
#pragma unroll
        for (int t = 0; t < 8; t++) {
            float p00 = __expf(s[t][0] - mn0);
            float p01 = __expf(s[t][1] - mn0);
            float p10 = __expf(s[t][2] - mn1);
            float p11 = __expf(s[t][3] - mn1);
            rs0 += p00 + p01; rs1 += p10 + p11;
            pph[t][0] = pack_fp16(p00, p01);
            pph[t][1] = pack_fp16(p10, p11);
        }
        rs0 += __shfl_xor_sync(0xffffffffu, rs0, 1);
        rs0 += __shfl_xor_sync(0xffffffffu, rs0, 2);
        rs1 += __shfl_xor_sync(0xffffffffu, rs1, 1);
        rs1 += __shfl_xor_sync(0xffffffffu, rs1, 2);
        l0 = l0 * al0 + rs0;
        l1 = l1 * al1 + rs1;
#pragma unroll
        for (int t = 0; t < 8; t++) {
            o[t][0] *= al0; o[t][1] *= al0;
            o[t][2] *= al1; o[t][3] *= al1;
        }

#pragma unroll
        for (int ks = 0; ks < 4; ks++) {
            uint32_t ah[4] = { pph[2*ks][0], pph[2*ks][1], pph[2*ks+1][0], pph[2*ks+1][1] };
            int r = 16 * ks + vrow0;
            uint32_t rb = (uint32_t)r * 128;
            uint32_t rs = (uint32_t)(r & 7);
#pragma unroll
            for (int p = 0; p < 4; p++) {
                uint32_t c = (uint32_t)(2 * p) + vck;
                uint32_t off = rb + ((c ^ rs) << 4);
                uint32_t b0, b1, b2, b3;
                ldmatrix_x4_trans(b0, b1, b2, b3, sV + off);
                mma_fp16(o[2*p],   ah, b0, b1);
                mma_fp16(o[2*p+1], ah, b2, b3);
            }
        }
        __syncthreads();
    }

    float inv0 = 1.0f / l0, inv1 = 1.0f / l1;
    const int r0 = q0 + 16 * w + (lane >> 2);
    __half* out0 = O + (rowbase + r0) * Cn + h * Dn + (lane & 3) * 2;
    __half* out1 = out0 + 8 * Cn;
#pragma unroll
    for (int t = 0; t < 8; t++) {
        *(uint32_t*)(out0 + t * 8) = pack_fp16(o[t][0] * inv0, o[t][1] * inv0);
        *(uint32_t*)(out1 + t * 8) = pack_fp16(o[t][2] * inv1, o[t][3] * inv1);
    }
}

// ---------------------------------------------------------------------------
extern "C" void kernel_launch(void* const* d_in, const int* in_sizes, int n_in,
                              void* d_out, int out_size)
{
    const float* x    = (const float*)d_in[0];
    const float* cosp = (const float*)d_in[1];
    const float* sinp = (const float*)d_in[2];
    const float* Wq   = (const float*)d_in[3];
    const float* Wk   = (const float*)d_in[4];
    const float* Wv   = (const float*)d_in[5];
    const float* Wo   = (const float*)d_in[6];
    float* out = (float*)d_out;

    __half *x16, *w16, *a16, *q16, *k16, *v16;
    cudaGetSymbolAddress((void**)&x16, g_x16);
    cudaGetSymbolAddress((void**)&w16, g_w16);
    cudaGetSymbolAddress((void**)&a16, g_a16);
    cudaGetSymbolAddress((void**)&q16, g_q16);
    cudaGetSymbolAddress((void**)&k16, g_k16);
    cudaGetSymbolAddress((void**)&v16, g_v16);

    cudaFuncSetAttribute(flash_tc,
                         cudaFuncAttributeMaxDynamicSharedMemorySize, FLASH_SMEM);

    const size_t WSZ = (size_t)Cn * Cn;

    // operand conversion: x (1 launch) + all 4 weights (1 launch)
    conv_fp16<<<(Mn * Cn / 4 + 255) / 256, 256>>>(x, x16, Mn * Cn / 4);
    conv_w4<<<dim3(Cn * Cn / 4 / 256, 4), 256>>>(Wq, Wk, Wv, Wo, w16);

    // fused QKV projection (Wq|Wk|Wv contiguous in g_w16), fp16 out
    gemm_qkv<<<dim3(3 * Cn / 128, Mn / 128), 256>>>(x16, w16, q16, k16, v16);

    // RoPE + RMS-norm in place on fp16 Q, K
    rope_rms_fp16<<<(Mn * Hn) / 8, 256>>>(q16, k16, cosp, sinp);

    dim3 fg(Tn / 64, Hn, Bn);      // (32, 16, 4)
    flash_tc<<<fg, 128, FLASH_SMEM>>>(q16, k16, v16, a16);

    gemm_fp16<<<dim3(Cn / 128, Mn / 128), 256>>>(a16, w16 + 3 * WSZ, out, Mn, Cn, Cn);
}

// round 15
// speedup vs baseline: 1.0001x; 1.0001x over previous
#include <cuda_runtime.h>
#include <cuda_fp16.h>
#include <math.h>
#include <stdint.h>

// Problem constants
#define Bn 4
#define Tn 2048
#define Cn 1024
#define Hn 16
#define Dn 64
#define Mn (Bn*Tn)   // 8192 token rows

// fp16 operands (g_w16 contiguous: rows [0,3072) = Wq|Wk|Wv, [3072,4096) = Wo)
__device__ __half g_x16[(size_t)Mn*Cn];
__device__ __half g_w16[4][(size_t)Cn*Cn];
__device__ __half g_a16[(size_t)Mn*Cn];    // attention output
__device__ __half g_q16[(size_t)Mn*Cn];    // Q (post-GEMM; rope in place, scaled 1/8)
__device__ __half g_k16[(size_t)Mn*Cn];    // K
__device__ __half g_v16[(size_t)Mn*Cn];    // V

// ---------------------------------------------------------------------------
// common PTX helpers
// ---------------------------------------------------------------------------
static __device__ __forceinline__ void cp_async16(uint32_t dst, const void* src) {
    asm volatile("cp.async.cg.shared.global [%0], [%1], 16;\n" :: "r"(dst), "l"(src));
}
static __device__ __forceinline__ void cp_commit() {
    asm volatile("cp.async.commit_group;\n");
}
static __device__ __forceinline__ void cp_wait1() {
    asm volatile("cp.async.wait_group 1;\n");
}
static __device__ __forceinline__ void ldmatrix_x4(uint32_t &r0, uint32_t &r1,
                                                   uint32_t &r2, uint32_t &r3, uint32_t addr) {
    asm volatile("ldmatrix.sync.aligned.m8n8.x4.shared.b16 {%0,%1,%2,%3}, [%4];\n"
                 : "=r"(r0), "=r"(r1), "=r"(r2), "=r"(r3) : "r"(addr));
}
static __device__ __forceinline__ void ldmatrix_x4_trans(uint32_t &r0, uint32_t &r1,
                                                         uint32_t &r2, uint32_t &r3, uint32_t addr) {
    asm volatile("ldmatrix.sync.aligned.m8n8.x4.trans.shared.b16 {%0,%1,%2,%3}, [%4];\n"
                 : "=r"(r0), "=r"(r1), "=r"(r2), "=r"(r3) : "r"(addr));
}
static __device__ __forceinline__ void mma_fp16(float* d, const uint32_t* a,
                                                uint32_t b0, uint32_t b1) {
    asm volatile(
        "mma.sync.aligned.m16n8k16.row.col.f32.f16.f16.f32 "
        "{%0,%1,%2,%3}, {%4,%5,%6,%7}, {%8,%9}, {%0,%1,%2,%3};\n"
        : "+f"(d[0]), "+f"(d[1]), "+f"(d[2]), "+f"(d[3])
        : "r"(a[0]), "r"(a[1]), "r"(a[2]), "r"(a[3]), "r"(b0), "r"(b1));
}
static __device__ __forceinline__ uint32_t pack_fp16(float lo, float hi) {
    uint32_t d;
    asm volatile("cvt.rn.f16x2.f32 %0, %1, %2;\n" : "=r"(d) : "f"(hi), "f"(lo));
    return d;
}

// ---------------------------------------------------------------------------
// fp32 -> fp16 converts
// ---------------------------------------------------------------------------
__global__ __launch_bounds__(256) void conv_fp16(
    const float* __restrict__ src, __half* __restrict__ dst, int n4)
{
    int i = blockIdx.x * 256 + threadIdx.x;
    if (i >= n4) return;
    float4 v = ((const float4*)src)[i];
    uint2 o;
    o.x = pack_fp16(v.x, v.y);
    o.y = pack_fp16(v.z, v.w);
    ((uint2*)dst)[i] = o;
}

__global__ __launch_bounds__(256) void conv_w4(
    const float* __restrict__ w0, const float* __restrict__ w1,
    const float* __restrict__ w2, const float* __restrict__ w3,
    __half* __restrict__ dst)
{
    const float* srcs[4] = { w0, w1, w2, w3 };
    const int m = blockIdx.y;
    const int i = blockIdx.x * 256 + threadIdx.x;   // < Cn*Cn/4
    float4 v = ((const float4*)srcs[m])[i];
    uint2 o;
    o.x = pack_fp16(v.x, v.y);
    o.y = pack_fp16(v.z, v.w);
    ((uint2*)(dst + (size_t)m * Cn * Cn))[i] = o;
}

// ---------------------------------------------------------------------------
// Shared GEMM mainloop pieces (128x128x32 tile, 8 warps, m16n8k16.f16)
// ---------------------------------------------------------------------------
#define BM 128
#define BN 128
#define BKH 32
#define STAGES 3
#define ATILE_BYTES (BM*BKH*2)          // 8192
#define STAGE_BYTES (2*ATILE_BYTES)     // 16384

// The mainloop body is duplicated in two kernels that differ only in epilogue.

// ---- QKV fused GEMM: A[M,K] * Wqkv[3072,K]^T, fp16 outputs split by matrix ----
__global__ __launch_bounds__(256) void gemm_qkv(
    const __half* __restrict__ A, const __half* __restrict__ W,
    __half* __restrict__ Q, __half* __restrict__ Ko, __half* __restrict__ V)
{
    __shared__ __align__(16) char smem[STAGES * STAGE_BYTES];
    const int K = Cn;

    const int tid  = threadIdx.x;
    const int lane = tid & 31;
    const int wid  = tid >> 5;
    const int wm   = wid >> 2;
    const int wn   = wid & 3;
    const int rowBase = blockIdx.y * BM;
    const int colBase = blockIdx.x * BN;    // 0..2944

    const uint32_t sbase = (uint32_t)__cvta_generic_to_shared(smem);

    const int lr = tid >> 2;
    const int lc = tid & 3;
    const uint32_t swz = (uint32_t)(lc ^ ((lr >> 1) & 3));
    const uint32_t dA0 = sbase + (uint32_t)lr * 64 + (swz << 4);
    const __half* pA0 = A + (size_t)(rowBase + lr) * K + lc * 8;
    const __half* pA1 = A + (size_t)(rowBase + lr + 64) * K + lc * 8;
    const __half* pW0 = W + (size_t)(colBase + lr) * K + lc * 8;
    const __half* pW1 = W + (size_t)(colBase + lr + 64) * K + lc * 8;

    uint32_t aoff[4]; uint32_t asw[4];
#pragma unroll
    for (int mt = 0; mt < 4; mt++) {
        int r = wm * 64 + mt * 16 + (lane & 15);
        aoff[mt] = (uint32_t)r * 64;
        asw[mt]  = (uint32_t)((r >> 1) & 3);
    }
    const uint32_t alo = (uint32_t)((lane >> 4) & 1);
    uint32_t boff[2]; uint32_t bsw[2];
#pragma unroll
    for (int p = 0; p < 2; p++) {
        int r = wn * 32 + p * 16 + ((lane >> 4) << 3) + (lane & 7);
        boff[p] = (uint32_t)(ATILE_BYTES) + (uint32_t)r * 64;
        bsw[p]  = (uint32_t)((r >> 1) & 3);
    }
    const uint32_t blo = (uint32_t)((lane >> 3) & 1);

    float acc[4][4][4];
#pragma unroll
    for (int i = 0; i < 4; i++)
#pragma unroll
        for (int j = 0; j < 4; j++)
#pragma unroll
            for (int v = 0; v < 4; v++) acc[i][j][v] = 0.0f;

    const int nIters = K / BKH;

#pragma unroll
    for (int s = 0; s < 2; s++) {
        uint32_t sb = dA0 + s * STAGE_BYTES;
        int k0 = s * BKH;
        cp_async16(sb,                    pA0 + k0);
        cp_async16(sb + 4096,             pA1 + k0);
        cp_async16(sb + ATILE_BYTES,      pW0 + k0);
        cp_async16(sb + ATILE_BYTES+4096, pW1 + k0);
        cp_commit();
    }

    for (int it = 0; it < nIters; ++it) {
        cp_wait1();
        __syncthreads();

        if (it + 2 < nIters) {
            uint32_t sb = dA0 + ((it + 2) % STAGES) * STAGE_BYTES;
            int k0 = (it + 2) * BKH;
            cp_async16(sb,                    pA0 + k0);
            cp_async16(sb + 4096,             pA1 + k0);
            cp_async16(sb + ATILE_BYTES,      pW0 + k0);
            cp_async16(sb + ATILE_BYTES+4096, pW1 + k0);
        }
        cp_commit();

        const uint32_t sb = sbase + (uint32_t)((it % STAGES) * STAGE_BYTES);
#pragma unroll
        for (int ks = 0; ks < 2; ks++) {
            uint32_t a[4][4], b[4][2];
#pragma unroll
            for (int mt = 0; mt < 4; mt++) {
                uint32_t c = (uint32_t)(2 * ks) + alo;
                uint32_t addr = sb + aoff[mt] + ((c ^ asw[mt]) << 4);
                ldmatrix_x4(a[mt][0], a[mt][1], a[mt][2], a[mt][3], addr);
            }
#pragma unroll
            for (int p = 0; p < 2; p++) {
                uint32_t c = (uint32_t)(2 * ks) + blo;
                uint32_t addr = sb + boff[p] + ((c ^ bsw[p]) << 4);
                uint32_t r0, r1, r2, r3;
                ldmatrix_x4(r0, r1, r2, r3, addr);
                b[2*p][0] = r0; b[2*p][1] = r1;
                b[2*p+1][0] = r2; b[2*p+1][1] = r3;
            }
#pragma unroll
            for (int mt = 0; mt < 4; mt++)
#pragma unroll
                for (int nt = 0; nt < 4; nt++)
                    mma_fp16(acc[mt][nt], a[mt], b[nt][0], b[nt][1]);
        }
    }

    // epilogue: fp16 to the matrix selected by colBase
    const int matsel = colBase >> 10;           // 0=Q 1=K 2=V
    const int ccb    = colBase & 1023;
    __half* dst = (matsel == 0) ? Q : (matsel == 1) ? Ko : V;
#pragma unroll
    for (int mt = 0; mt < 4; mt++) {
        int r0 = rowBase + wm * 64 + mt * 16 + (lane >> 2);
#pragma unroll
        for (int nt = 0; nt < 4; nt++) {
            int cc = ccb + wn * 32 + nt * 8 + (lane & 3) * 2;
            *(uint32_t*)(dst + (size_t)r0 * Cn + cc) =
                pack_fp16(acc[mt][nt][0], acc[mt][nt][1]);
            *(uint32_t*)(dst + (size_t)(r0 + 8) * Cn + cc) =
                pack_fp16(acc[mt][nt][2], acc[mt][nt][3]);
        }
    }
}

// ---- Output projection GEMM: fp32 out ----
__global__ __launch_bounds__(256) void gemm_fp16(
    const __half* __restrict__ A, const __half* __restrict__ W,
    float* __restrict__ C, int M, int N, int K)
{
    __shared__ __align__(16) char smem[STAGES * STAGE_BYTES];

    const int tid  = threadIdx.x;
    const int lane = tid & 31;
    const int wid  = tid >> 5;
    const int wm   = wid >> 2;
    const int wn   = wid & 3;
    const int rowBase = blockIdx.y * BM;
    const int colBase = blockIdx.x * BN;

    const uint32_t sbase = (uint32_t)__cvta_generic_to_shared(smem);

    const int lr = tid >> 2;
    const int lc = tid & 3;
    const uint32_t swz = (uint32_t)(lc ^ ((lr >> 1) & 3));
    const uint32_t dA0 = sbase + (uint32_t)lr * 64 + (swz << 4);
    const __half* pA0 = A + (size_t)(rowBase + lr) * K + lc * 8;
    const __half* pA1 = A + (size_t)(rowBase + lr + 64) * K + lc * 8;
    const __half* pW0 = W + (size_t)(colBase + lr) * K + lc * 8;
    const __half* pW1 = W + (size_t)(colBase + lr + 64) * K + lc * 8;

    uint32_t aoff[4]; uint32_t asw[4];
#pragma unroll
    for (int mt = 0; mt < 4; mt++) {
        int r = wm * 64 + mt * 16 + (lane & 15);
        aoff[mt] = (uint32_t)r * 64;
        asw[mt]  = (uint32_t)((r >> 1) & 3);
    }
    const uint32_t alo = (uint32_t)((lane >> 4) & 1);
    uint32_t boff[2]; uint32_t bsw[2];
#pragma unroll
    for (int p = 0; p < 2; p++) {
        int r = wn * 32 + p * 16 + ((lane >> 4) << 3) + (lane & 7);
        boff[p] = (uint32_t)(ATILE_BYTES) + (uint32_t)r * 64;
        bsw[p]  = (uint32_t)((r >> 1) & 3);
    }
    const uint32_t blo = (uint32_t)((lane >> 3) & 1);

    float acc[4][4][4];
#pragma unroll
    for (int i = 0; i < 4; i++)
#pragma unroll
        for (int j = 0; j < 4; j++)
#pragma unroll
            for (int v = 0; v < 4; v++) acc[i][j][v] = 0.0f;

    const int nIters = K / BKH;

#pragma unroll
    for (int s = 0; s < 2; s++) {
        uint32_t sb = dA0 + s * STAGE_BYTES;
        int k0 = s * BKH;
        cp_async16(sb,                    pA0 + k0);
        cp_async16(sb + 4096,             pA1 + k0);
        cp_async16(sb + ATILE_BYTES,      pW0 + k0);
        cp_async16(sb + ATILE_BYTES+4096, pW1 + k0);
        cp_commit();
    }

    for (int it = 0; it < nIters; ++it) {
        cp_wait1();
        __syncthreads();

        if (it + 2 < nIters) {
            uint32_t sb = dA0 + ((it + 2) % STAGES) * STAGE_BYTES;
            int k0 = (it + 2) * BKH;
            cp_async16(sb,                    pA0 + k0);
            cp_async16(sb + 4096,             pA1 + k0);
            cp_async16(sb + ATILE_BYTES,      pW0 + k0);
            cp_async16(sb + ATILE_BYTES+4096, pW1 + k0);
        }
        cp_commit();

        const uint32_t sb = sbase + (uint32_t)((it % STAGES) * STAGE_BYTES);
#pragma unroll
        for (int ks = 0; ks < 2; ks++) {
            uint32_t a[4][4], b[4][2];
#pragma unroll
            for (int mt = 0; mt < 4; mt++) {
                uint32_t c = (uint32_t)(2 * ks) + alo;
                uint32_t addr = sb + aoff[mt] + ((c ^ asw[mt]) << 4);
                ldmatrix_x4(a[mt][0], a[mt][1], a[mt][2], a[mt][3], addr);
            }
#pragma unroll
            for (int p = 0; p < 2; p++) {
                uint32_t c = (uint32_t)(2 * ks) + blo;
                uint32_t addr = sb + boff[p] + ((c ^ bsw[p]) << 4);
                uint32_t r0, r1, r2, r3;
                ldmatrix_x4(r0, r1, r2, r3, addr);
                b[2*p][0] = r0; b[2*p][1] = r1;
                b[2*p+1][0] = r2; b[2*p+1][1] = r3;
            }
#pragma unroll
            for (int mt = 0; mt < 4; mt++)
#pragma unroll
                for (int nt = 0; nt < 4; nt++)
                    mma_fp16(acc[mt][nt], a[mt], b[nt][0], b[nt][1]);
        }
    }

#pragma unroll
    for (int mt = 0; mt < 4; mt++) {
        int r0 = rowBase + wm * 64 + mt * 16 + (lane >> 2);
#pragma unroll
        for (int nt = 0; nt < 4; nt++) {
            int cc = colBase + wn * 32 + nt * 8 + (lane & 3) * 2;
            *(float2*)(C + (size_t)r0 * N + cc) =
                make_float2(acc[mt][nt][0], acc[mt][nt][1]);
            *(float2*)(C + (size_t)(r0 + 8) * N + cc) =
                make_float2(acc[mt][nt][2], acc[mt][nt][3]);
        }
    }
}

// ---------------------------------------------------------------------------
// Fused RoPE + RMS-norm, IN PLACE on fp16 Q and K (Q post-scaled by 1/8).
// One warp per (token_row, head); lane holds dims lane and lane+32.
// ---------------------------------------------------------------------------
__global__ __launch_bounds__(256) void rope_rms_fp16(
    __half* __restrict__ q16, __half* __restrict__ k16,
    const float* __restrict__ cp, const float* __restrict__ sp)
{
    const int gw   = (blockIdx.x * 256 + threadIdx.x) >> 5;
    const int lane = threadIdx.x & 31;
    const int row  = gw >> 4;
    const int head = gw & 15;
    const int t    = row & (Tn - 1);

    const float c1 = cp[t * Dn + lane];
    const float c2 = cp[t * Dn + 32 + lane];
    const float s1 = sp[t * Dn + lane];
    const float s2 = sp[t * Dn + 32 + lane];

    const size_t base = (size_t)row * Cn + head * Dn;
    __half* bufs[2] = { q16 + base, k16 + base };
    const float postscale[2] = { 0.125f, 1.0f };

#pragma unroll
    for (int p = 0; p < 2; p++) {
        __half* buf = bufs[p];
        float x1 = __half2float(buf[lane]);
        float x2 = __half2float(buf[lane + 32]);
        float r1 = x1 * c1 - x2 * s1;
        float r2 = x2 * c2 + x1 * s2;
        float ss = r1 * r1 + r2 * r2;
#pragma unroll
        for (int off = 16; off >= 1; off >>= 1)
            ss += __shfl_xor_sync(0xffffffffu, ss, off);
        float scale = rsqrtf(ss * (1.0f / 64.0f) + 1e-6f) * postscale[p];
        buf[lane]      = __float2half(r1 * scale);
        buf[lane + 32] = __float2half(r2 * scale);
    }
}

// ---------------------------------------------------------------------------
// Tensor-core flash attention, single fp16, fp32 accumulate. (unchanged)
// ---------------------------------------------------------------------------
#define F_Q 0
#define F_ST 8192
#define F_TILE 8192
#define F_STAGE 16384
#define FLASH_SMEM (8192 + 2*16384)   // 40960

static __device__ __forceinline__ void load_tile64(uint32_t sdst,
                                                   const __half* g, int tid)
{
    int r = tid >> 1;
    int cb = (tid & 1) * 4;
    const char* src = (const char*)g + (size_t)r * (Cn * 2);
#pragma unroll
    for (int i = 0; i < 4; i++) {
        int c = cb + i;
        cp_async16(sdst + (uint32_t)r * 128 + (uint32_t)((c ^ (r & 7)) << 4),
                   src + c * 16);
    }
}

__global__ __launch_bounds__(128) void flash_tc(
    const __half* __restrict__ q16, const __half* __restrict__ k16,
    const __half* __restrict__ v16, __half* __restrict__ O)
{
    extern __shared__ __align__(1024) char smem[];
    const uint32_t sb = (uint32_t)__cvta_generic_to_shared(smem);

    const int tid  = threadIdx.x;
    const int w    = tid >> 5;
    const int lane = tid & 31;
    const int q0   = blockIdx.x * 64;
    const int h    = blockIdx.y;
    const int b    = blockIdx.z;
    const size_t rowbase = (size_t)b * Tn;
    const size_t qgoff = (rowbase + q0) * Cn + h * Dn;
    const size_t kgoff = rowbase * Cn + h * Dn;

    load_tile64(sb + F_Q, q16 + qgoff, tid);
    load_tile64(sb + F_ST + 0*F_TILE, k16 + kgoff, tid);
    load_tile64(sb + F_ST + 1*F_TILE, v16 + kgoff, tid);
    cp_commit();

    const int qrow = 16 * w + ((lane >> 3) & 1) * 8 + (lane & 7);
    const uint32_t qrb = (uint32_t)qrow * 128;
    const uint32_t qrs = (uint32_t)(qrow & 7);
    const uint32_t ahi = (uint32_t)(lane >> 4);
    const int krow0 = (lane >> 4) * 8 + (lane & 7);
    const uint32_t kck = (uint32_t)((lane >> 3) & 1);
    const int vrow0 = ((lane >> 3) & 1) * 8 + (lane & 7);
    const uint32_t vck = (uint32_t)(lane >> 4);

    float o[8][4];
#pragma unroll
    for (int t = 0; t < 8; t++)
#pragma unroll
        for (int j = 0; j < 4; j++) o[t][j] = 0.0f;
    float m0 = -1e30f, m1 = -1e30f, l0 = 0.0f, l1 = 0.0f;

    const int NKT = Tn / 64;
    for (int kt = 0; kt < NKT; kt++) {
        if (kt + 1 < NKT) {
            const size_t goff = kgoff + (size_t)(kt + 1) * 64 * Cn;
            uint32_t st = sb + F_ST + ((kt + 1) & 1) * F_STAGE;
            load_tile64(st,          k16 + goff, tid);
            load_tile64(st + F_TILE, v16 + goff, tid);
        }
        cp_commit();
        cp_wait1();
        __syncthreads();

        const uint32_t st = sb + F_ST + (kt & 1) * F_STAGE;
        const uint32_t sK = st, sV = st + F_TILE;

        float s[8][4];
#pragma unroll
        for (int t = 0; t < 8; t++)
#pragma unroll
            for (int j = 0; j < 4; j++) s[t][j] = 0.0f;

#pragma unroll
        for (int ks = 0; ks < 4; ks++) {
            uint32_t aq[4];
            {
                uint32_t c = (uint32_t)(2 * ks) + ahi;
                uint32_t off = qrb + ((c ^ qrs) << 4);
                ldmatrix_x4(aq[0], aq[1], aq[2], aq[3], sb + F_Q + off);
            }
#pragma unroll
            for (int p = 0; p < 4; p++) {
                int r = 16 * p + krow0;
                uint32_t c = (uint32_t)(2 * ks) + kck;
                uint32_t off = (uint32_t)r * 128 + ((c ^ (uint32_t)(r & 7)) << 4);
                uint32_t b0, b1, b2, b3;
                ldmatrix_x4(b0, b1, b2, b3, sK + off);
                mma_fp16(s[2*p],   aq, b0, b1);
                mma_fp16(s[2*p+1], aq, b2, b3);
            }
        }

        float mx0 = -1e30f, mx1 = -1e30f;
#pragma unroll
        for (int t = 0; t < 8; t++) {
            mx0 = fmaxf(mx0, fmaxf(s[t][0], s[t][1]));
            mx1 = fmaxf(mx1, fmaxf(s[t][2], s[t][3]));
        }
        mx0 = fmaxf(mx0, __shfl_xor_sync(0xffffffffu, mx0, 1));
        mx0 = fmaxf(mx0, __shfl_xor_sync(0xffffffffu, mx0, 2));
        mx1 = fmaxf(mx1, __shfl_xor_sync(0xffffffffu, mx1, 1));
        mx1 = fmaxf(mx1, __shfl_xor_sync(0xffffffffu, mx1, 2));
        float mn0 = fmaxf(m0, mx0), mn1 = fmaxf(m1, mx1);
        float al0 = __expf(m0 - mn0), al1 = __expf(m1 - mn1);
        m0 = mn0; m1 = mn1;

        float rs0 = 0.0f, rs1 = 0.0f;
        uint32_t pph[8][2];
#pragma unroll
        for (int t = 0; t < 8; t++) {
            float p00 = __expf(s[t][0] - mn0);
            float p01 = __expf(s[t][1] - mn0);
            float p10 = __expf(s[t][2] - mn1);
            float p11 = __expf(s[t][3] - mn1);
            rs0 += p00 + p01; rs1 += p10 + p11;
            pph[t][0] = pack_fp16(p00, p01);
            pph[t][1] = pack_fp16(p10, p11);
        }
        rs0 += __shfl_xor_sync(0xffffffffu, rs0, 1);
        rs0 += __shfl_xor_sync(0xffffffffu, rs0, 2);
        rs1 += __shfl_xor_sync(0xffffffffu, rs1, 1);
        rs1 += __shfl_xor_sync(0xffffffffu, rs1, 2);
        l0 = l0 * al0 + rs0;
        l1 = l1 * al1 + rs1;
#pragma unroll
        for (int t = 0; t < 8; t++) {
            o[t][0] *= al0; o[t][1] *= al0;
            o[t][2] *= al1; o[t][3] *= al1;
        }

#pragma unroll
        for (int ks = 0; ks < 4; ks++) {
            uint32_t ah[4] = { pph[2*ks][0], pph[2*ks][1], pph[2*ks+1][0], pph[2*ks+1][1] };
            int r = 16 * ks + vrow0;
            uint32_t rb = (uint32_t)r * 128;
            uint32_t rs = (uint32_t)(r & 7);
#pragma unroll
            for (int p = 0; p < 4; p++) {
                uint32_t c = (uint32_t)(2 * p) + vck;
                uint32_t off = rb + ((c ^ rs) << 4);
                uint32_t b0, b1, b2, b3;
                ldmatrix_x4_trans(b0, b1, b2, b3, sV + off);
                mma_fp16(o[2*p],   ah, b0, b1);
                mma_fp16(o[2*p+1], ah, b2, b3);
            }
        }
        __syncthreads();
    }

    float inv0 = 1.0f / l0, inv1 = 1.0f / l1;
    const int r0 = q0 + 16 * w + (lane >> 2);
    __half* out0 = O + (rowbase + r0) * Cn + h * Dn + (lane & 3) * 2;
    __half* out1 = out0 + 8 * Cn;
#pragma unroll
    for (int t = 0; t < 8; t++) {
        *(uint32_t*)(out0 + t * 8) = pack_fp16(o[t][0] * inv0, o[t][1] * inv0);
        *(uint32_t*)(out1 + t * 8) = pack_fp16(o[t][2] * inv1, o[t][3] * inv1);
    }
}

// ---------------------------------------------------------------------------
extern "C" void kernel_launch(void* const* d_in, const int* in_sizes, int n_in,
                              void* d_out, int out_size)
{
    const float* x    = (const float*)d_in[0];
    const float* cosp = (const float*)d_in[1];
    const float* sinp = (const float*)d_in[2];
    const float* Wq   = (const float*)d_in[3];
    const float* Wk   = (const float*)d_in[4];
    const float* Wv   = (const float*)d_in[5];
    const float* Wo   = (const float*)d_in[6];
    float* out = (float*)d_out;

    __half *x16, *w16, *a16, *q16, *k16, *v16;
    cudaGetSymbolAddress((void**)&x16, g_x16);
    cudaGetSymbolAddress((void**)&w16, g_w16);
    cudaGetSymbolAddress((void**)&a16, g_a16);
    cudaGetSymbolAddress((void**)&q16, g_q16);
    cudaGetSymbolAddress((void**)&k16, g_k16);
    cudaGetSymbolAddress((void**)&v16, g_v16);

    cudaFuncSetAttribute(flash_tc,
                         cudaFuncAttributeMaxDynamicSharedMemorySize, FLASH_SMEM);

    const size_t WSZ = (size_t)Cn * Cn;

    // operand conversion: x (1 launch) + all 4 weights (1 launch)
    conv_fp16<<<(Mn * Cn / 4 + 255) / 256, 256>>>(x, x16, Mn * Cn / 4);
    conv_w4<<<dim3(Cn * Cn / 4 / 256, 4), 256>>>(Wq, Wk, Wv, Wo, w16);

    // fused QKV projection (Wq|Wk|Wv contiguous in g_w16), fp16 out
    gemm_qkv<<<dim3(3 * Cn / 128, Mn / 128), 256>>>(x16, w16, q16, k16, v16);

    // RoPE + RMS-norm in place on fp16 Q, K
    rope_rms_fp16<<<(Mn * Hn) / 8, 256>>>(q16, k16, cosp, sinp);

    dim3 fg(Tn / 64, Hn, Bn);      // (32, 16, 4)
    flash_tc<<<fg, 128, FLASH_SMEM>>>(q16, k16, v16, a16);

    gemm_fp16<<<dim3(Cn / 128, Mn / 128), 256>>>(a16, w16 + 3 * WSZ, out, Mn, Cn, Cn);
}

// round 16
// speedup vs baseline: 1.0032x; 1.0032x over previous
#include <cuda_runtime.h>
#include <cuda_fp16.h>
#include <math.h>
#include <stdint.h>

// Problem constants
#define Bn 4
#define Tn 2048
#define Cn 1024
#define Hn 16
#define Dn 64
#define Mn (Bn*Tn)   // 8192 token rows

// fp16 operands (g_w16 contiguous: rows [0,3072) = Wq|Wk|Wv, [3072,4096) = Wo)
__device__ __half g_x16[(size_t)Mn*Cn];
__device__ __half g_w16[4][(size_t)Cn*Cn];
__device__ __half g_a16[(size_t)Mn*Cn];    // attention output
__device__ __half g_q16[(size_t)Mn*Cn];    // Q (post-GEMM; rope in place, scaled 1/8)
__device__ __half g_k16[(size_t)Mn*Cn];    // K
__device__ __half g_v16[(size_t)Mn*Cn];    // V

// ---------------------------------------------------------------------------
// common PTX helpers
// ---------------------------------------------------------------------------
static __device__ __forceinline__ void cp_async16(uint32_t dst, const void* src) {
    asm volatile("cp.async.cg.shared.global [%0], [%1], 16;\n" :: "r"(dst), "l"(src));
}
static __device__ __forceinline__ void cp_commit() {
    asm volatile("cp.async.commit_group;\n");
}
static __device__ __forceinline__ void cp_wait1() {
    asm volatile("cp.async.wait_group 1;\n");
}
static __device__ __forceinline__ void ldmatrix_x4(uint32_t &r0, uint32_t &r1,
                                                   uint32_t &r2, uint32_t &r3, uint32_t addr) {
    asm volatile("ldmatrix.sync.aligned.m8n8.x4.shared.b16 {%0,%1,%2,%3}, [%4];\n"
                 : "=r"(r0), "=r"(r1), "=r"(r2), "=r"(r3) : "r"(addr));
}
static __device__ __forceinline__ void ldmatrix_x4_trans(uint32_t &r0, uint32_t &r1,
                                                         uint32_t &r2, uint32_t &r3, uint32_t addr) {
    asm volatile("ldmatrix.sync.aligned.m8n8.x4.trans.shared.b16 {%0,%1,%2,%3}, [%4];\n"
                 : "=r"(r0), "=r"(r1), "=r"(r2), "=r"(r3) : "r"(addr));
}
static __device__ __forceinline__ void mma_fp16(float* d, const uint32_t* a,
                                                uint32_t b0, uint32_t b1) {
    asm volatile(
        "mma.sync.aligned.m16n8k16.row.col.f32.f16.f16.f32 "
        "{%0,%1,%2,%3}, {%4,%5,%6,%7}, {%8,%9}, {%0,%1,%2,%3};\n"
        : "+f"(d[0]), "+f"(d[1]), "+f"(d[2]), "+f"(d[3])
        : "r"(a[0]), "r"(a[1]), "r"(a[2]), "r"(a[3]), "r"(b0), "r"(b1));
}
static __device__ __forceinline__ uint32_t pack_fp16(float lo, float hi) {
    uint32_t d;
    asm volatile("cvt.rn.f16x2.f32 %0, %1, %2;\n" : "=r"(d) : "f"(hi), "f"(lo));
    return d;
}

// ---------------------------------------------------------------------------
// fp32 -> fp16 converts
// ---------------------------------------------------------------------------
__global__ __launch_bounds__(256) void conv_fp16(
    const float* __restrict__ src, __half* __restrict__ dst, int n4)
{
    int i = blockIdx.x * 256 + threadIdx.x;
    if (i >= n4) return;
    float4 v = ((const float4*)src)[i];
    uint2 o;
    o.x = pack_fp16(v.x, v.y);
    o.y = pack_fp16(v.z, v.w);
    ((uint2*)dst)[i] = o;
}

__global__ __launch_bounds__(256) void conv_w4(
    const float* __restrict__ w0, const float* __restrict__ w1,
    const float* __restrict__ w2, const float* __restrict__ w3,
    __half* __restrict__ dst)
{
    const float* srcs[4] = { w0, w1, w2, w3 };
    const int m = blockIdx.y;
    const int i = blockIdx.x * 256 + threadIdx.x;   // < Cn*Cn/4
    float4 v = ((const float4*)srcs[m])[i];
    uint2 o;
    o.x = pack_fp16(v.x, v.y);
    o.y = pack_fp16(v.z, v.w);
    ((uint2*)(dst + (size_t)m * Cn * Cn))[i] = o;
}

// ---------------------------------------------------------------------------
// Shared GEMM mainloop pieces (128x128x32 tile, 8 warps, m16n8k16.f16)
// ---------------------------------------------------------------------------
#define BM 128
#define BN 128
#define BKH 32
#define STAGES 3
#define ATILE_BYTES (BM*BKH*2)          // 8192
#define STAGE_BYTES (2*ATILE_BYTES)     // 16384

// The mainloop body is duplicated in two kernels that differ only in epilogue.

// ---- QKV fused GEMM: A[M,K] * Wqkv[3072,K]^T, fp16 outputs split by matrix ----
__global__ __launch_bounds__(256) void gemm_qkv(
    const __half* __restrict__ A, const __half* __restrict__ W,
    __half* __restrict__ Q, __half* __restrict__ Ko, __half* __restrict__ V)
{
    __shared__ __align__(16) char smem[STAGES * STAGE_BYTES];
    const int K = Cn;

    const int tid  = threadIdx.x;
    const int lane = tid & 31;
    const int wid  = tid >> 5;
    const int wm   = wid >> 2;
    const int wn   = wid & 3;
    const int rowBase = blockIdx.y * BM;
    const int colBase = blockIdx.x * BN;    // 0..2944

    const uint32_t sbase = (uint32_t)__cvta_generic_to_shared(smem);

    const int lr = tid >> 2;
    const int lc = tid & 3;
    const uint32_t swz = (uint32_t)(lc ^ ((lr >> 1) & 3));
    const uint32_t dA0 = sbase + (uint32_t)lr * 64 + (swz << 4);
    const __half* pA0 = A + (size_t)(rowBase + lr) * K + lc * 8;
    const __half* pA1 = A + (size_t)(rowBase + lr + 64) * K + lc * 8;
    const __half* pW0 = W + (size_t)(colBase + lr) * K + lc * 8;
    const __half* pW1 = W + (size_t)(colBase + lr + 64) * K + lc * 8;

    uint32_t aoff[4]; uint32_t asw[4];
#pragma unroll
    for (int mt = 0; mt < 4; mt++) {
        int r = wm * 64 + mt * 16 + (lane & 15);
        aoff[mt] = (uint32_t)r * 64;
        asw[mt]  = (uint32_t)((r >> 1) & 3);
    }
    const uint32_t alo = (uint32_t)((lane >> 4) & 1);
    uint32_t boff[2]; uint32_t bsw[2];
#pragma unroll
    for (int p = 0; p < 2; p++) {
        int r = wn * 32 + p * 16 + ((lane >> 4) << 3) + (lane & 7);
        boff[p] = (uint32_t)(ATILE_BYTES) + (uint32_t)r * 64;
        bsw[p]  = (uint32_t)((r >> 1) & 3);
    }
    const uint32_t blo = (uint32_t)((lane >> 3) & 1);

    float acc[4][4][4];
#pragma unroll
    for (int i = 0; i < 4; i++)
#pragma unroll
        for (int j = 0; j < 4; j++)
#pragma unroll
            for (int v = 0; v < 4; v++) acc[i][j][v] = 0.0f;

    const int nIters = K / BKH;

#pragma unroll
    for (int s = 0; s < 2; s++) {
        uint32_t sb = dA0 + s * STAGE_BYTES;
        int k0 = s * BKH;
        cp_async16(sb,                    pA0 + k0);
        cp_async16(sb + 4096,             pA1 + k0);
        cp_async16(sb + ATILE_BYTES,      pW0 + k0);
        cp_async16(sb + ATILE_BYTES+4096, pW1 + k0);
        cp_commit();
    }

    for (int it = 0; it < nIters; ++it) {
        cp_wait1();
        __syncthreads();

        if (it + 2 < nIters) {
            uint32_t sb = dA0 + ((it + 2) % STAGES) * STAGE_BYTES;
            int k0 = (it + 2) * BKH;
            cp_async16(sb,                    pA0 + k0);
            cp_async16(sb + 4096,             pA1 + k0);
            cp_async16(sb + ATILE_BYTES,      pW0 + k0);
            cp_async16(sb + ATILE_BYTES+4096, pW1 + k0);
        }
        cp_commit();

        const uint32_t sb = sbase + (uint32_t)((it % STAGES) * STAGE_BYTES);
#pragma unroll
        for (int ks = 0; ks < 2; ks++) {
            uint32_t a[4][4], b[4][2];
#pragma unroll
            for (int mt = 0; mt < 4; mt++) {
                uint32_t c = (uint32_t)(2 * ks) + alo;
                uint32_t addr = sb + aoff[mt] + ((c ^ asw[mt]) << 4);
                ldmatrix_x4(a[mt][0], a[mt][1], a[mt][2], a[mt][3], addr);
            }
#pragma unroll
            for (int p = 0; p < 2; p++) {
                uint32_t c = (uint32_t)(2 * ks) + blo;
                uint32_t addr = sb + boff[p] + ((c ^ bsw[p]) << 4);
                uint32_t r0, r1, r2, r3;
                ldmatrix_x4(r0, r1, r2, r3, addr);
                b[2*p][0] = r0; b[2*p][1] = r1;
                b[2*p+1][0] = r2; b[2*p+1][1] = r3;
            }
#pragma unroll
            for (int mt = 0; mt < 4; mt++)
#pragma unroll
                for (int nt = 0; nt < 4; nt++)
                    mma_fp16(acc[mt][nt], a[mt], b[nt][0], b[nt][1]);
        }
    }

    // epilogue: fp16 to the matrix selected by colBase
    const int matsel = colBase >> 10;           // 0=Q 1=K 2=V
    const int ccb    = colBase & 1023;
    __half* dst = (matsel == 0) ? Q : (matsel == 1) ? Ko : V;
#pragma unroll
    for (int mt = 0; mt < 4; mt++) {
        int r0 = rowBase + wm * 64 + mt * 16 + (lane >> 2);
#pragma unroll
        for (int nt = 0; nt < 4; nt++) {
            int cc = ccb + wn * 32 + nt * 8 + (lane & 3) * 2;
            *(uint32_t*)(dst + (size_t)r0 * Cn + cc) =
                pack_fp16(acc[mt][nt][0], acc[mt][nt][1]);
            *(uint32_t*)(dst + (size_t)(r0 + 8) * Cn + cc) =
                pack_fp16(acc[mt][nt][2], acc[mt][nt][3]);
        }
    }
}

// ---- Output projection GEMM: fp32 out ----
__global__ __launch_bounds__(256) void gemm_fp16(
    const __half* __restrict__ A, const __half* __restrict__ W,
    float* __restrict__ C, int M, int N, int K)
{
    __shared__ __align__(16) char smem[STAGES * STAGE_BYTES];

    const int tid  = threadIdx.x;
    const int lane = tid & 31;
    const int wid  = tid >> 5;
    const int wm   = wid >> 2;
    const int wn   = wid & 3;
    const int rowBase = blockIdx.y * BM;
    const int colBase = blockIdx.x * BN;

    const uint32_t sbase = (uint32_t)__cvta_generic_to_shared(smem);

    const int lr = tid >> 2;
    const int lc = tid & 3;
    const uint32_t swz = (uint32_t)(lc ^ ((lr >> 1) & 3));
    const uint32_t dA0 = sbase + (uint32_t)lr * 64 + (swz << 4);
    const __half* pA0 = A + (size_t)(rowBase + lr) * K + lc * 8;
    const __half* pA1 = A + (size_t)(rowBase + lr + 64) * K + lc * 8;
    const __half* pW0 = W + (size_t)(colBase + lr) * K + lc * 8;
    const __half* pW1 = W + (size_t)(colBase + lr + 64) * K + lc * 8;

    uint32_t aoff[4]; uint32_t asw[4];
#pragma unroll
    for (int mt = 0; mt < 4; mt++) {
        int r = wm * 64 + mt * 16 + (lane & 15);
        aoff[mt] = (uint32_t)r * 64;
        asw[mt]  = (uint32_t)((r >> 1) & 3);
    }
    const uint32_t alo = (uint32_t)((lane >> 4) & 1);
    uint32_t boff[2]; uint32_t bsw[2];
#pragma unroll
    for (int p = 0; p < 2; p++) {
        int r = wn * 32 + p * 16 + ((lane >> 4) << 3) + (lane & 7);
        boff[p] = (uint32_t)(ATILE_BYTES) + (uint32_t)r * 64;
        bsw[p]  = (uint32_t)((r >> 1) & 3);
    }
    const uint32_t blo = (uint32_t)((lane >> 3) & 1);

    float acc[4][4][4];
#pragma unroll
    for (int i = 0; i < 4; i++)
#pragma unroll
        for (int j = 0; j < 4; j++)
#pragma unroll
            for (int v = 0; v < 4; v++) acc[i][j][v] = 0.0f;

    const int nIters = K / BKH;

#pragma unroll
    for (int s = 0; s < 2; s++) {
        uint32_t sb = dA0 + s * STAGE_BYTES;
        int k0 = s * BKH;
        cp_async16(sb,                    pA0 + k0);
        cp_async16(sb + 4096,             pA1 + k0);
        cp_async16(sb + ATILE_BYTES,      pW0 + k0);
        cp_async16(sb + ATILE_BYTES+4096, pW1 + k0);
        cp_commit();
    }

    for (int it = 0; it < nIters; ++it) {
        cp_wait1();
        __syncthreads();

        if (it + 2 < nIters) {
            uint32_t sb = dA0 + ((it + 2) % STAGES) * STAGE_BYTES;
            int k0 = (it + 2) * BKH;
            cp_async16(sb,                    pA0 + k0);
            cp_async16(sb + 4096,             pA1 + k0);
            cp_async16(sb + ATILE_BYTES,      pW0 + k0);
            cp_async16(sb + ATILE_BYTES+4096, pW1 + k0);
        }
        cp_commit();

        const uint32_t sb = sbase + (uint32_t)((it % STAGES) * STAGE_BYTES);
#pragma unroll
        for (int ks = 0; ks < 2; ks++) {
            uint32_t a[4][4], b[4][2];
#pragma unroll
            for (int mt = 0; mt < 4; mt++) {
                uint32_t c = (uint32_t)(2 * ks) + alo;
                uint32_t addr = sb + aoff[mt] + ((c ^ asw[mt]) << 4);
                ldmatrix_x4(a[mt][0], a[mt][1], a[mt][2], a[mt][3], addr);
            }
#pragma unroll
            for (int p = 0; p < 2; p++) {
                uint32_t c = (uint32_t)(2 * ks) + blo;
                uint32_t addr = sb + boff[p] + ((c ^ bsw[p]) << 4);
                uint32_t r0, r1, r2, r3;
                ldmatrix_x4(r0, r1, r2, r3, addr);
                b[2*p][0] = r0; b[2*p][1] = r1;
                b[2*p+1][0] = r2; b[2*p+1][1] = r3;
            }
#pragma unroll
            for (int mt = 0; mt < 4; mt++)
#pragma unroll
                for (int nt = 0; nt < 4; nt++)
                    mma_fp16(acc[mt][nt], a[mt], b[nt][0], b[nt][1]);
        }
    }

#pragma unroll
    for (int mt = 0; mt < 4; mt++) {
        int r0 = rowBase + wm * 64 + mt * 16 + (lane >> 2);
#pragma unroll
        for (int nt = 0; nt < 4; nt++) {
            int cc = colBase + wn * 32 + nt * 8 + (lane & 3) * 2;
            *(float2*)(C + (size_t)r0 * N + cc) =
                make_float2(acc[mt][nt][0], acc[mt][nt][1]);
            *(float2*)(C + (size_t)(r0 + 8) * N + cc) =
                make_float2(acc[mt][nt][2], acc[mt][nt][3]);
        }
    }
}

// ---------------------------------------------------------------------------
// Fused RoPE + RMS-norm, IN PLACE on fp16 Q and K (Q post-scaled by 1/8).
// One warp per (token_row, head); lane holds dims lane and lane+32.
// ---------------------------------------------------------------------------
__global__ __launch_bounds__(256) void rope_rms_fp16(
    __half* __restrict__ q16, __half* __restrict__ k16,
    const float* __restrict__ cp, const float* __restrict__ sp)
{
    const int gw   = (blockIdx.x * 256 + threadIdx.x) >> 5;
    const int lane = threadIdx.x & 31;
    const int row  = gw >> 4;
    const int head = gw & 15;
    const int t    = row & (Tn - 1);

    const float c1 = cp[t * Dn + lane];
    const float c2 = cp[t * Dn + 32 + lane];
    const float s1 = sp[t * Dn + lane];
    const float s2 = sp[t * Dn + 32 + lane];

    const size_t base = (size_t)row * Cn + head * Dn;
    __half* bufs[2] = { q16 + base, k16 + base };
    const float postscale[2] = { 0.125f, 1.0f };

#pragma unroll
    for (int p = 0; p < 2; p++) {
        __half* buf = bufs[p];
        float x1 = __half2float(buf[lane]);
        float x2 = __half2float(buf[lane + 32]);
        float r1 = x1 * c1 - x2 * s1;
        float r2 = x2 * c2 + x1 * s2;
        float ss = r1 * r1 + r2 * r2;
#pragma unroll
        for (int off = 16; off >= 1; off >>= 1)
            ss += __shfl_xor_sync(0xffffffffu, ss, off);
        float scale = rsqrtf(ss * (1.0f / 64.0f) + 1e-6f) * postscale[p];
        buf[lane]      = __float2half(r1 * scale);
        buf[lane + 32] = __float2half(r2 * scale);
    }
}

// ---------------------------------------------------------------------------
// Tensor-core flash attention, single fp16, fp32 accumulate. (unchanged)
// ---------------------------------------------------------------------------
#define F_Q 0
#define F_ST 8192
#define F_TILE 8192
#define F_STAGE 16384
#define FLASH_SMEM (8192 + 2*16384)   // 40960

static __device__ __forceinline__ void load_tile64(uint32_t sdst,
                                                   const __half* g, int tid)
{
    int r = tid >> 1;
    int cb = (tid & 1) * 4;
    const char* src = (const char*)g + (size_t)r * (Cn * 2);
#pragma unroll
    for (int i = 0; i < 4; i++) {
        int c = cb + i;
        cp_async16(sdst + (uint32_t)r * 128 + (uint32_t)((c ^ (r & 7)) << 4),
                   src + c * 16);
    }
}

__global__ __launch_bounds__(128) void flash_tc(
    const __half* __restrict__ q16, const __half* __restrict__ k16,
    const __half* __restrict__ v16, __half* __restrict__ O)
{
    extern __shared__ __align__(1024) char smem[];
    const uint32_t sb = (uint32_t)__cvta_generic_to_shared(smem);

    const int tid  = threadIdx.x;
    const int w    = tid >> 5;
    const int lane = tid & 31;
    const int q0   = blockIdx.x * 64;
    const int h    = blockIdx.y;
    const int b    = blockIdx.z;
    const size_t rowbase = (size_t)b * Tn;
    const size_t qgoff = (rowbase + q0) * Cn + h * Dn;
    const size_t kgoff = rowbase * Cn + h * Dn;

    load_tile64(sb + F_Q, q16 + qgoff, tid);
    load_tile64(sb + F_ST + 0*F_TILE, k16 + kgoff, tid);
    load_tile64(sb + F_ST + 1*F_TILE, v16 + kgoff, tid);
    cp_commit();

    const int qrow = 16 * w + ((lane >> 3) & 1) * 8 + (lane & 7);
    const uint32_t qrb = (uint32_t)qrow * 128;
    const uint32_t qrs = (uint32_t)(qrow & 7);
    const uint32_t ahi = (uint32_t)(lane >> 4);
    const int krow0 = (lane >> 4) * 8 + (lane & 7);
    const uint32_t kck = (uint32_t)((lane >> 3) & 1);
    const int vrow0 = ((lane >> 3) & 1) * 8 + (lane & 7);
    const uint32_t vck = (uint32_t)(lane >> 4);

    float o[8][4];
#pragma unroll
    for (int t = 0; t < 8; t++)
#pragma unroll
        for (int j = 0; j < 4; j++) o[t][j] = 0.0f;
    float m0 = -1e30f, m1 = -1e30f, l0 = 0.0f, l1 = 0.0f;

    const int NKT = Tn / 64;
    for (int kt = 0; kt < NKT; kt++) {
        if (kt + 1 < NKT) {
            const size_t goff = kgoff + (size_t)(kt + 1) * 64 * Cn;
            uint32_t st = sb + F_ST + ((kt + 1) & 1) * F_STAGE;
            load_tile64(st,          k16 + goff, tid);
            load_tile64(st + F_TILE, v16 + goff, tid);
        }
        cp_commit();
        cp_wait1();
        __syncthreads();

        const uint32_t st = sb + F_ST + (kt & 1) * F_STAGE;
        const uint32_t sK = st, sV = st + F_TILE;

        float s[8][4];
#pragma unroll
        for (int t = 0; t < 8; t++)
#pragma unroll
            for (int j = 0; j < 4; j++) s[t][j] = 0.0f;

#pragma unroll
        for (int ks = 0; ks < 4; ks++) {
            uint32_t aq[4];
            {
                uint32_t c = (uint32_t)(2 * ks) + ahi;
                uint32_t off = qrb + ((c ^ qrs) << 4);
                ldmatrix_x4(aq[0], aq[1], aq[2], aq[3], sb + F_Q + off);
            }
#pragma unroll
            for (int p = 0; p < 4; p++) {
                int r = 16 * p + krow0;
                uint32_t c = (uint32_t)(2 * ks) + kck;
                uint32_t off = (uint32_t)r * 128 + ((c ^ (uint32_t)(r & 7)) << 4);
                uint32_t b0, b1, b2, b3;
                ldmatrix_x4(b0, b1, b2, b3, sK + off);
                mma_fp16(s[2*p],   aq, b0, b1);
                mma_fp16(s[2*p+1], aq, b2, b3);
            }
        }

        float mx0 = -1e30f, mx1 = -1e30f;
#pragma unroll
        for (int t = 0; t < 8; t++) {
            mx0 = fmaxf(mx0, fmaxf(s[t][0], s[t][1]));
            mx1 = fmaxf(mx1, fmaxf(s[t][2], s[t][3]));
        }
        mx0 = fmaxf(mx0, __shfl_xor_sync(0xffffffffu, mx0, 1));
        mx0 = fmaxf(mx0, __shfl_xor_sync(0xffffffffu, mx0, 2));
        mx1 = fmaxf(mx1, __shfl_xor_sync(0xffffffffu, mx1, 1));
        mx1 = fmaxf(mx1, __shfl_xor_sync(0xffffffffu, mx1, 2));
        float mn0 = fmaxf(m0, mx0), mn1 = fmaxf(m1, mx1);
        float al0 = __expf(m0 - mn0), al1 = __expf(m1 - mn1);
        m0 = mn0; m1 = mn1;

        float rs0 = 0.0f, rs1 = 0.0f;
        uint32_t pph[8][2];
#pragma unroll
        for (int t = 0; t < 8; t++) {
            float p00 = __expf(s[t][0] - mn0);
            float p01 = __expf(s[t][1] - mn0);
            float p10 = __expf(s[t][2] - mn1);
            float p11 = __expf(s[t][3] - mn1);
            rs0 += p00 + p01; rs1 += p10 + p11;
            pph[t][0] = pack_fp16(p00, p01);
            pph[t][1] = pack_fp16(p10, p11);
        }
        rs0 += __shfl_xor_sync(0xffffffffu, rs0, 1);
        rs0 += __shfl_xor_sync(0xffffffffu, rs0, 2);
        rs1 += __shfl_xor_sync(0xffffffffu, rs1, 1);
        rs1 += __shfl_xor_sync(0xffffffffu, rs1, 2);
        l0 = l0 * al0 + rs0;
        l1 = l1 * al1 + rs1;
#pragma unroll
        for (int t = 0; t < 8; t++) {
            o[t][0] *= al0; o[t][1] *= al0;
            o[t][2] *= al1; o[t][3] *= al1;
        }

#pragma unroll
        for (int ks = 0; ks < 4; ks++) {
            uint32_t ah[4] = { pph[2*ks][0], pph[2*ks][1], pph[2*ks+1][0], pph[2*ks+1][1] };
            int r = 16 * ks + vrow0;
            uint32_t rb = (uint32_t)r * 128;
            uint32_t rs = (uint32_t)(r & 7);
#pragma unroll
            for (int p = 0; p < 4; p++) {
                uint32_t c = (uint32_t)(2 * p) + vck;
                uint32_t off = rb + ((c ^ rs) << 4);
                uint32_t b0, b1, b2, b3;
                ldmatrix_x4_trans(b0, b1, b2, b3, sV + off);
                mma_fp16(o[2*p],   ah, b0, b1);
                mma_fp16(o[2*p+1], ah, b2, b3);
            }
        }
        __syncthreads();
    }

    float inv0 = 1.0f / l0, inv1 = 1.0f / l1;
    const int r0 = q0 + 16 * w + (lane >> 2);
    __half* out0 = O + (rowbase + r0) * Cn + h * Dn + (lane & 3) * 2;
    __half* out1 = out0 + 8 * Cn;
#pragma unroll
    for (int t = 0; t < 8; t++) {
        *(uint32_t*)(out0 + t * 8) = pack_fp16(o[t][0] * inv0, o[t][1] * inv0);
        *(uint32_t*)(out1 + t * 8) = pack_fp16(o[t][2] * inv1, o[t][3] * inv1);
    }
}

// ---------------------------------------------------------------------------
extern "C" void kernel_launch(void* const* d_in, const int* in_sizes, int n_in,
                              void* d_out, int out_size)
{
    const float* x    = (const float*)d_in[0];
    const float* cosp = (const float*)d_in[1];
    const float* sinp = (const float*)d_in[2];
    const float* Wq   = (const float*)d_in[3];
    const float* Wk   = (const float*)d_in[4];
    const float* Wv   = (const float*)d_in[5];
    const float* Wo   = (const float*)d_in[6];
    float* out = (float*)d_out;

    __half *x16, *w16, *a16, *q16, *k16, *v16;
    cudaGetSymbolAddress((void**)&x16, g_x16);
    cudaGetSymbolAddress((void**)&w16, g_w16);
    cudaGetSymbolAddress((void**)&a16, g_a16);
    cudaGetSymbolAddress((void**)&q16, g_q16);
    cudaGetSymbolAddress((void**)&k16, g_k16);
    cudaGetSymbolAddress((void**)&v16, g_v16);

    cudaFuncSetAttribute(flash_tc,
                         cudaFuncAttributeMaxDynamicSharedMemorySize, FLASH_SMEM);

    const size_t WSZ = (size_t)Cn * Cn;

    // operand conversion: x (1 launch) + all 4 weights (1 launch)
    conv_fp16<<<(Mn * Cn / 4 + 255) / 256, 256>>>(x, x16, Mn * Cn / 4);
    conv_w4<<<dim3(Cn * Cn / 4 / 256, 4), 256>>>(Wq, Wk, Wv, Wo, w16);

    // fused QKV projection (Wq|Wk|Wv contiguous in g_w16), fp16 out
    gemm_qkv<<<dim3(3 * Cn / 128, Mn / 128), 256>>>(x16, w16, q16, k16, v16);

    // RoPE + RMS-norm in place on fp16 Q, K
    rope_rms_fp16<<<(Mn * Hn) / 8, 256>>>(q16, k16, cosp, sinp);

    dim3 fg(Tn / 64, Hn, Bn);      // (32, 16, 4)
    flash_tc<<<fg, 128, FLASH_SMEM>>>(q16, k16, v16, a16);

    gemm_fp16<<<dim3(Cn / 128, Mn / 128), 256>>>(a16, w16 + 3 * WSZ, out, Mn, Cn, Cn);
}